// round 1
// baseline (speedup 1.0000x reference)
#include <cuda_runtime.h>
#include <cuda_bf16.h>

// IrradiationSingleTimestep — fully fused single-kernel implementation.
// Nested 5-point periodic stencil handled via shared-memory tiling:
//   load (TS+4)^2 halo of cv/ci/eta  -> compute dF_dcv/dF_dci on (TS+2)^2
//   (writing eta_new directly for interior points) -> outer Laplacian of dF
//   -> cv_new / ci_new on TS^2.
// Periodic wrap uses & (1024-1) (valid for the small negative offsets here).

#define WID   1024
#define HEI   1024
#define BAT   8
#define TS    32
#define IN_W  (TS + 4)   // 36: input tile with 2-halo
#define DF_W  (TS + 2)   // 34: dF tile with 1-halo
#define EPSV  1e-6f
#define DTV   1e-2f

__global__ __launch_bounds__(TS * TS, 1)
void irr_fused_kernel(const float* __restrict__ cv_g,
                      const float* __restrict__ ci_g,
                      const float* __restrict__ eta_g,
                      const float* __restrict__ p_ev,
                      const float* __restrict__ p_ei,
                      const float* __restrict__ p_kbt,
                      const float* __restrict__ p_kv,
                      const float* __restrict__ p_ki,
                      const float* __restrict__ p_ke,
                      const float* __restrict__ p_dv,
                      const float* __restrict__ p_di,
                      const float* __restrict__ p_L,
                      float* __restrict__ out)
{
    __shared__ float s_cv [IN_W][IN_W];
    __shared__ float s_ci [IN_W][IN_W];
    __shared__ float s_eta[IN_W][IN_W];
    __shared__ float s_dfv[DF_W][DF_W];
    __shared__ float s_dfi[DF_W][DF_W];

    const int lx  = threadIdx.x;
    const int ly  = threadIdx.y;
    const int tid = ly * TS + lx;
    const int bx  = blockIdx.x * TS;
    const int by  = blockIdx.y * TS;
    const int b   = blockIdx.z;

    const size_t plane = (size_t)WID * HEI;          // 1M elements
    const size_t fld   = (size_t)BAT * plane;        // 8M elements (per output field)
    const size_t base  = (size_t)b * plane;

    // Scalar parameters (uniform; broadcast loads hit L1).
    const float energy_v  = fabsf(*p_ev)  + 0.001f;
    const float energy_i  = fabsf(*p_ei)  + 0.001f;
    const float kBT       = fabsf(*p_kbt) + 0.001f;
    const float kappa_v   = fabsf(*p_kv)  + 0.001f;
    const float kappa_i   = fabsf(*p_ki)  + 0.001f;
    const float kappa_eta = fabsf(*p_ke)  + 0.001f;
    const float diff_v    = fabsf(*p_dv)  + 0.001f;
    const float diff_i    = fabsf(*p_di)  + 0.001f;
    const float Lp        = fabsf(*p_L)   + 0.001f;
    const float inv_kBT   = 1.0f / kBT;

    // ---- Phase 1: cooperative halo load (periodic wrap) ----
    #pragma unroll
    for (int i = tid; i < IN_W * IN_W; i += TS * TS) {
        const int r  = i / IN_W;
        const int c  = i - r * IN_W;
        const int gy = (by + r - 2) & (HEI - 1);
        const int gx = (bx + c - 2) & (WID - 1);
        const size_t g = base + (size_t)gy * WID + gx;
        s_cv [r][c] = cv_g [g];
        s_ci [r][c] = ci_g [g];
        s_eta[r][c] = eta_g[g];
    }
    __syncthreads();

    // ---- Phase 2: dF_dcv / dF_dci on DF_W x DF_W; eta_new for interior ----
    for (int i = tid; i < DF_W * DF_W; i += TS * TS) {
        const int py = i / DF_W;
        const int px = i - py * DF_W;
        const int sy = py + 1;
        const int sx = px + 1;

        const float cv  = s_cv [sy][sx];
        const float ci  = s_ci [sy][sx];
        const float eta = s_eta[sy][sx];

        const float lap_cv = s_cv[sy][sx-1] + s_cv[sy][sx+1]
                           + s_cv[sy-1][sx] + s_cv[sy+1][sx] - 4.0f * cv;
        const float lap_ci = s_ci[sy][sx-1] + s_ci[sy][sx+1]
                           + s_ci[sy-1][sx] + s_ci[sy+1][sx] - 4.0f * ci;

        const float cs  = 1.0f - cv - ci;
        const float lcv = __logf(fmaxf(cv, EPSV));
        const float lci = __logf(fmaxf(ci, EPSV));
        const float lcs = __logf(fmaxf(cs, EPSV));

        const float em1 = eta - 1.0f;
        const float h   = em1 * em1;
        const float jj  = eta * eta;

        const float dfs_dcv = energy_v + kBT * (lcv - lcs);
        const float dfs_dci = energy_i + kBT * (lci - lcs);

        const float dfv = h * dfs_dcv + jj * (2.0f * (cv - 1.0f)) - kappa_v * lap_cv;
        const float dfi = h * dfs_dci + jj * (2.0f * ci)          - kappa_i * lap_ci;

        s_dfv[py][px] = dfv;
        s_dfi[py][px] = dfi;

        // eta_new only needs one Laplacian level -> finish it here for the
        // interior (true output) region.
        if (px >= 1 && px < DF_W - 1 && py >= 1 && py < DF_W - 1) {
            const float lap_eta = s_eta[sy][sx-1] + s_eta[sy][sx+1]
                                + s_eta[sy-1][sx] + s_eta[sy+1][sx] - 4.0f * eta;
            const float fs = energy_v * cv + energy_i * ci
                           + kBT * (cv * lcv + ci * lci + cs * lcs);
            const float cvm1 = cv - 1.0f;
            const float fv   = cvm1 * cvm1 + ci * ci;
            const float dFe  = fs * (2.0f * em1) + fv * (2.0f * eta)
                             - kappa_eta * lap_eta;
            float eta_new = eta - DTV * (Lp * dFe);
            eta_new = fminf(fmaxf(eta_new, 0.0f), 1.0f);

            const int ox = bx + px - 1;
            const int oy = by + py - 1;
            out[2 * fld + base + (size_t)oy * WID + ox] = eta_new;
        }
    }
    __syncthreads();

    // ---- Phase 3: outer Laplacian of dF -> cv_new / ci_new ----
    {
        const int px = lx + 1;
        const int py = ly + 1;

        const float dfv_c = s_dfv[py][px];
        const float dfi_c = s_dfi[py][px];
        const float lap_dfv = s_dfv[py][px-1] + s_dfv[py][px+1]
                            + s_dfv[py-1][px] + s_dfv[py+1][px] - 4.0f * dfv_c;
        const float lap_dfi = s_dfi[py][px-1] + s_dfi[py][px+1]
                            + s_dfi[py-1][px] + s_dfi[py+1][px] - 4.0f * dfi_c;

        const float cv = s_cv[ly + 2][lx + 2];
        const float ci = s_ci[ly + 2][lx + 2];

        const float mv = diff_v * cv * inv_kBT;
        const float mi = diff_i * ci * inv_kBT;

        float cv_new = cv + DTV * (mv * lap_dfv);
        float ci_new = ci + DTV * (mi * lap_dfi);
        cv_new = fminf(fmaxf(cv_new, 0.0f), 1.0f);
        ci_new = fminf(fmaxf(ci_new, 0.0f), 1.0f);

        const size_t o = base + (size_t)(by + ly) * WID + (bx + lx);
        out[o]       = cv_new;
        out[fld + o] = ci_new;
    }
}

extern "C" void kernel_launch(void* const* d_in, const int* in_sizes, int n_in,
                              void* d_out, int out_size)
{
    const float* cv  = (const float*)d_in[0];
    const float* ci  = (const float*)d_in[1];
    const float* eta = (const float*)d_in[2];
    const float* ev  = (const float*)d_in[3];
    const float* ei  = (const float*)d_in[4];
    const float* kbt = (const float*)d_in[5];
    const float* kv  = (const float*)d_in[6];
    const float* ki  = (const float*)d_in[7];
    const float* ke  = (const float*)d_in[8];
    const float* dv  = (const float*)d_in[9];
    const float* di  = (const float*)d_in[10];
    const float* L   = (const float*)d_in[11];
    float* out = (float*)d_out;

    dim3 block(TS, TS, 1);
    dim3 grid(WID / TS, HEI / TS, BAT);
    irr_fused_kernel<<<grid, block>>>(cv, ci, eta, ev, ei, kbt, kv, ki, ke,
                                      dv, di, L, out);
}

// round 2
// speedup vs baseline: 2.3712x; 2.3712x over previous
#include <cuda_runtime.h>
#include <cuda_bf16.h>

// IrradiationSingleTimestep — fused nested-stencil kernel, round 2.
// 32x32 output tile, 256-thread (32x8) blocks, x4 thread coarsening.
// Aim: multiple CTAs/SM for latency hiding (was 1x1024-thread CTA, occ 49%).

#define WID   1024
#define HEI   1024
#define BAT   8
#define TSX   32
#define TSY   32
#define BDY   8              // block is 32 x 8
#define IN_W  (TSX + 4)      // 36: input tile with 2-halo
#define DF_W  (TSX + 2)      // 34: dF tile with 1-halo
#define EPSV  1e-6f
#define DTV   1e-2f

__global__ __launch_bounds__(TSX * BDY, 6)
void irr_fused_kernel(const float* __restrict__ cv_g,
                      const float* __restrict__ ci_g,
                      const float* __restrict__ eta_g,
                      const float* __restrict__ p_ev,
                      const float* __restrict__ p_ei,
                      const float* __restrict__ p_kbt,
                      const float* __restrict__ p_kv,
                      const float* __restrict__ p_ki,
                      const float* __restrict__ p_ke,
                      const float* __restrict__ p_dv,
                      const float* __restrict__ p_di,
                      const float* __restrict__ p_L,
                      float* __restrict__ out)
{
    __shared__ float s_cv [IN_W][IN_W];
    __shared__ float s_ci [IN_W][IN_W];
    __shared__ float s_eta[IN_W][IN_W];
    __shared__ float s_dfv[DF_W][DF_W];
    __shared__ float s_dfi[DF_W][DF_W];

    const int lx  = threadIdx.x;           // 0..31
    const int ly  = threadIdx.y;           // 0..7
    const int tid = ly * TSX + lx;         // 0..255
    const int bx  = blockIdx.x * TSX;
    const int by  = blockIdx.y * TSY;
    const int b   = blockIdx.z;

    const size_t plane = (size_t)WID * HEI;
    const size_t fld   = (size_t)BAT * plane;
    const size_t base  = (size_t)b * plane;

    const float energy_v  = fabsf(*p_ev)  + 0.001f;
    const float energy_i  = fabsf(*p_ei)  + 0.001f;
    const float kBT       = fabsf(*p_kbt) + 0.001f;
    const float kappa_v   = fabsf(*p_kv)  + 0.001f;
    const float kappa_i   = fabsf(*p_ki)  + 0.001f;
    const float kappa_eta = fabsf(*p_ke)  + 0.001f;
    const float diff_v    = fabsf(*p_dv)  + 0.001f;
    const float diff_i    = fabsf(*p_di)  + 0.001f;
    const float Lp        = fabsf(*p_L)   + 0.001f;
    const float inv_kBT   = 1.0f / kBT;

    // ---- Phase 1: halo load (periodic wrap), no integer div ----
    #pragma unroll
    for (int r = ly; r < IN_W; r += BDY) {
        const int gy = (by + r - 2) & (HEI - 1);
        const size_t rowb = base + (size_t)gy * WID;
        {
            const int gx = (bx + lx - 2) & (WID - 1);
            s_cv [r][lx] = cv_g [rowb + gx];
            s_ci [r][lx] = ci_g [rowb + gx];
            s_eta[r][lx] = eta_g[rowb + gx];
        }
        if (lx < IN_W - TSX) {                    // 4 extra columns
            const int c  = TSX + lx;
            const int gx = (bx + c - 2) & (WID - 1);
            s_cv [r][c] = cv_g [rowb + gx];
            s_ci [r][c] = ci_g [rowb + gx];
            s_eta[r][c] = eta_g[rowb + gx];
        }
    }
    __syncthreads();

    // ---- Phase 2: dF fields on 34x34 + eta_new (store predicated only) ----
    #pragma unroll
    for (int i = tid; i < DF_W * DF_W; i += TSX * BDY) {
        const int py = i / DF_W;                  // const-div -> mul/shift
        const int px = i - py * DF_W;
        const int sy = py + 1;
        const int sx = px + 1;

        const float cv  = s_cv [sy][sx];
        const float ci  = s_ci [sy][sx];
        const float eta = s_eta[sy][sx];

        const float lap_cv = s_cv[sy][sx-1] + s_cv[sy][sx+1]
                           + s_cv[sy-1][sx] + s_cv[sy+1][sx] - 4.0f * cv;
        const float lap_ci = s_ci[sy][sx-1] + s_ci[sy][sx+1]
                           + s_ci[sy-1][sx] + s_ci[sy+1][sx] - 4.0f * ci;
        const float lap_eta = s_eta[sy][sx-1] + s_eta[sy][sx+1]
                            + s_eta[sy-1][sx] + s_eta[sy+1][sx] - 4.0f * eta;

        const float cs  = 1.0f - cv - ci;
        const float lcv = __logf(fmaxf(cv, EPSV));
        const float lci = __logf(fmaxf(ci, EPSV));
        const float lcs = __logf(fmaxf(cs, EPSV));

        const float em1 = eta - 1.0f;
        const float h   = em1 * em1;
        const float jj  = eta * eta;

        const float dfs_dcv = energy_v + kBT * (lcv - lcs);
        const float dfs_dci = energy_i + kBT * (lci - lcs);

        s_dfv[py][px] = h * dfs_dcv + jj * (2.0f * (cv - 1.0f)) - kappa_v * lap_cv;
        s_dfi[py][px] = h * dfs_dci + jj * (2.0f * ci)          - kappa_i * lap_ci;

        // eta_new: compute unconditionally (branch-free), predicate the store.
        const float fs = energy_v * cv + energy_i * ci
                       + kBT * (cv * lcv + ci * lci + cs * lcs);
        const float cvm1 = cv - 1.0f;
        const float fv   = cvm1 * cvm1 + ci * ci;
        const float dFe  = fs * (2.0f * em1) + fv * (2.0f * eta)
                         - kappa_eta * lap_eta;
        float eta_new = eta - DTV * (Lp * dFe);
        eta_new = fminf(fmaxf(eta_new, 0.0f), 1.0f);

        if (px >= 1 && px < DF_W - 1 && py >= 1 && py < DF_W - 1) {
            out[2 * fld + base + (size_t)(by + py - 1) * WID + (bx + px - 1)] = eta_new;
        }
    }
    __syncthreads();

    // ---- Phase 3: outer Laplacian of dF -> cv_new / ci_new ----
    #pragma unroll
    for (int ry = ly; ry < TSY; ry += BDY) {
        const int px = lx + 1;
        const int py = ry + 1;

        const float dfv_c = s_dfv[py][px];
        const float dfi_c = s_dfi[py][px];
        const float lap_dfv = s_dfv[py][px-1] + s_dfv[py][px+1]
                            + s_dfv[py-1][px] + s_dfv[py+1][px] - 4.0f * dfv_c;
        const float lap_dfi = s_dfi[py][px-1] + s_dfi[py][px+1]
                            + s_dfi[py-1][px] + s_dfi[py+1][px] - 4.0f * dfi_c;

        const float cv = s_cv[ry + 2][lx + 2];
        const float ci = s_ci[ry + 2][lx + 2];

        const float mv = diff_v * cv * inv_kBT;
        const float mi = diff_i * ci * inv_kBT;

        float cv_new = cv + DTV * (mv * lap_dfv);
        float ci_new = ci + DTV * (mi * lap_dfi);
        cv_new = fminf(fmaxf(cv_new, 0.0f), 1.0f);
        ci_new = fminf(fmaxf(ci_new, 0.0f), 1.0f);

        const size_t o = base + (size_t)(by + ry) * WID + (bx + lx);
        out[o]       = cv_new;
        out[fld + o] = ci_new;
    }
}

extern "C" void kernel_launch(void* const* d_in, const int* in_sizes, int n_in,
                              void* d_out, int out_size)
{
    const float* cv  = (const float*)d_in[0];
    const float* ci  = (const float*)d_in[1];
    const float* eta = (const float*)d_in[2];
    const float* ev  = (const float*)d_in[3];
    const float* ei  = (const float*)d_in[4];
    const float* kbt = (const float*)d_in[5];
    const float* kv  = (const float*)d_in[6];
    const float* ki  = (const float*)d_in[7];
    const float* ke  = (const float*)d_in[8];
    const float* dv  = (const float*)d_in[9];
    const float* di  = (const float*)d_in[10];
    const float* L   = (const float*)d_in[11];
    float* out = (float*)d_out;

    dim3 block(TSX, BDY, 1);
    dim3 grid(WID / TSX, HEI / TSY, BAT);
    irr_fused_kernel<<<grid, block>>>(cv, ci, eta, ev, ei, kbt, kv, ki, ke,
                                      dv, di, L, out);
}

// round 3
// speedup vs baseline: 2.7391x; 1.1551x over previous
#include <cuda_runtime.h>
#include <cuda_bf16.h>

// IrradiationSingleTimestep — round 3: 4-wide vectorized fused stencil.
// Tile 64x16 output, input 72x20 (x-halo 4 each side so float4 groups are
// 16B-aligned; periodic wrap per 4-group is safe since 1024 % 4 == 0).
// All smem traffic is LDS.128/STS.128 + 2 edge scalars per group.

#define W     1024
#define BAT   8
#define TSX   64
#define TSY   16
#define NT    256            // 16 x 16 threads
#define SROW  76             // smem row stride (floats): 1 pad | 72 data @ col 4 | ...
#define NROW  20             // input rows (y-halo 2)
#define NG    18             // float4 groups per row (72 cols)
#define COFF  4              // data idx d lives at smem col COFF+d (16B aligned)
#define EPSV  1e-6f
#define DTV   1e-2f

#define SM_SZ (21 * SROW)    // one safety row for the idx+72 junk read

__device__ __forceinline__ float4 ld4(const float* s, int off) {
    return *(const float4*)(s + off);
}
__device__ __forceinline__ void st4(float* s, int off, float4 v) {
    *(float4*)(s + off) = v;
}
__device__ __forceinline__ float lane(const float4& v, int k) {
    return k == 0 ? v.x : (k == 1 ? v.y : (k == 2 ? v.z : v.w));
}
__device__ __forceinline__ void setlane(float4& v, int k, float x) {
    if (k == 0) v.x = x; else if (k == 1) v.y = x; else if (k == 2) v.z = x; else v.w = x;
}

// 5-point x-laplacian helper on a 4-vector with scalar edges (y terms added by caller)
__device__ __forceinline__ float4 lap4(float4 c, float L, float R, float4 u, float4 d) {
    float4 r;
    r.x = L   + c.y + u.x + d.x - 4.0f * c.x;
    r.y = c.x + c.z + u.y + d.y - 4.0f * c.y;
    r.z = c.y + c.w + u.z + d.z - 4.0f * c.z;
    r.w = c.z + R   + u.w + d.w - 4.0f * c.w;
    return r;
}

__global__ __launch_bounds__(NT, 5)
void irr_fused_kernel(const float* __restrict__ cv_g,
                      const float* __restrict__ ci_g,
                      const float* __restrict__ eta_g,
                      const float* __restrict__ p_ev,
                      const float* __restrict__ p_ei,
                      const float* __restrict__ p_kbt,
                      const float* __restrict__ p_kv,
                      const float* __restrict__ p_ki,
                      const float* __restrict__ p_ke,
                      const float* __restrict__ p_dv,
                      const float* __restrict__ p_di,
                      const float* __restrict__ p_L,
                      float* __restrict__ out)
{
    __shared__ alignas(16) float s_cv [SM_SZ];
    __shared__ alignas(16) float s_ci [SM_SZ];
    __shared__ alignas(16) float s_eta[SM_SZ];
    __shared__ alignas(16) float s_dfv[SM_SZ];
    __shared__ alignas(16) float s_dfi[SM_SZ];

    const int tx  = threadIdx.x;           // 0..15 (4-wide groups)
    const int ty  = threadIdx.y;           // 0..15
    const int tid = ty * 16 + tx;
    const int bx  = blockIdx.x * TSX;
    const int by  = blockIdx.y * TSY;
    const int b   = blockIdx.z;

    const size_t plane = (size_t)W * W;
    const size_t fld   = (size_t)BAT * plane;
    const size_t base  = (size_t)b * plane;

    const float energy_v  = fabsf(*p_ev)  + 0.001f;
    const float energy_i  = fabsf(*p_ei)  + 0.001f;
    const float kBT       = fabsf(*p_kbt) + 0.001f;
    const float kappa_v   = fabsf(*p_kv)  + 0.001f;
    const float kappa_i   = fabsf(*p_ki)  + 0.001f;
    const float kappa_eta = fabsf(*p_ke)  + 0.001f;
    const float diff_v    = fabsf(*p_dv)  + 0.001f;
    const float diff_i    = fabsf(*p_di)  + 0.001f;
    const float Lp        = fabsf(*p_L)   + 0.001f;
    const float inv_kBT   = 1.0f / kBT;

    // ---- Phase 1: vectorized halo load (periodic; 4-groups never split) ----
    #pragma unroll
    for (int t = tid; t < NROW * NG; t += NT) {
        const int r = t / NG;
        const int g = t - r * NG;
        const int gy = (by + r - 2) & (W - 1);
        const int gx = (bx - 4 + 4 * g) & (W - 1);
        const size_t goff = base + (size_t)gy * W + gx;
        const int soff = r * SROW + COFF + 4 * g;
        st4(s_cv,  soff, *(const float4*)&cv_g [goff]);
        st4(s_ci,  soff, *(const float4*)&ci_g [goff]);
        st4(s_eta, soff, *(const float4*)&eta_g[goff]);
    }
    __syncthreads();

    // ---- Phase 2: dF fields on rows 1..18, all 18 groups; eta_new fused ----
    #pragma unroll
    for (int t = tid; t < 18 * NG; t += NT) {
        const int q = t / NG;
        const int g = t - q * NG;
        const int r = q + 1;                    // 1..18
        const int c = r * SROW + COFF + 4 * g;  // center offset

        const float4 cv4 = ld4(s_cv, c);
        const float4 ci4 = ld4(s_ci, c);
        const float4 et4 = ld4(s_eta, c);

        const float4 lcv4 = lap4(cv4, s_cv[c-1],  s_cv[c+4],  ld4(s_cv,  c - SROW), ld4(s_cv,  c + SROW));
        const float4 lci4 = lap4(ci4, s_ci[c-1],  s_ci[c+4],  ld4(s_ci,  c - SROW), ld4(s_ci,  c + SROW));
        const float4 let4 = lap4(et4, s_eta[c-1], s_eta[c+4], ld4(s_eta, c - SROW), ld4(s_eta, c + SROW));

        float4 dfv4, dfi4, en4;
        #pragma unroll
        for (int k = 0; k < 4; k++) {
            const float cv  = lane(cv4, k);
            const float ci  = lane(ci4, k);
            const float eta = lane(et4, k);

            const float cs  = 1.0f - cv - ci;
            const float lcv = __logf(fmaxf(cv, EPSV));
            const float lci = __logf(fmaxf(ci, EPSV));
            const float lcs = __logf(fmaxf(cs, EPSV));

            const float em1 = eta - 1.0f;
            const float h   = em1 * em1;
            const float jj  = eta * eta;

            const float dfs_dcv = energy_v + kBT * (lcv - lcs);
            const float dfs_dci = energy_i + kBT * (lci - lcs);

            setlane(dfv4, k, h * dfs_dcv + jj * (2.0f * (cv - 1.0f)) - kappa_v * lane(lcv4, k));
            setlane(dfi4, k, h * dfs_dci + jj * (2.0f * ci)          - kappa_i * lane(lci4, k));

            const float fs = energy_v * cv + energy_i * ci
                           + kBT * (cv * lcv + ci * lci + cs * lcs);
            const float cvm1 = cv - 1.0f;
            const float fv   = cvm1 * cvm1 + ci * ci;
            const float dFe  = fs * (2.0f * em1) + fv * (2.0f * eta)
                             - kappa_eta * lane(let4, k);
            float en = eta - DTV * (Lp * dFe);
            setlane(en4, k, fminf(fmaxf(en, 0.0f), 1.0f));
        }

        st4(s_dfv, c, dfv4);
        st4(s_dfi, c, dfi4);

        // eta_new store: groups 1..16 (idx 4..67 -> out cols 0..63), rows 2..17
        if (g >= 1 && g <= 16 && r >= 2 && r <= 17) {
            const int ox = bx + 4 * g - 4;
            const int oy = by + r - 2;
            *(float4*)&out[2 * fld + base + (size_t)oy * W + ox] = en4;
        }
    }
    __syncthreads();

    // ---- Phase 3: outer Laplacian of dF -> cv_new / ci_new (1 task/thread) ----
    {
        const int r = ty + 2;                       // input row of output row ty
        const int c = r * SROW + COFF + 4 + 4 * tx; // dF idx = 4*tx+4

        const float4 dv4 = ld4(s_dfv, c);
        const float4 di4 = ld4(s_dfi, c);
        const float4 ldv = lap4(dv4, s_dfv[c-1], s_dfv[c+4], ld4(s_dfv, c - SROW), ld4(s_dfv, c + SROW));
        const float4 ldi = lap4(di4, s_dfi[c-1], s_dfi[c+4], ld4(s_dfi, c - SROW), ld4(s_dfi, c + SROW));

        const float4 cv4 = ld4(s_cv, c);
        const float4 ci4 = ld4(s_ci, c);

        float4 cvn, cin;
        #pragma unroll
        for (int k = 0; k < 4; k++) {
            const float cv = lane(cv4, k);
            const float ci = lane(ci4, k);
            const float mv = diff_v * cv * inv_kBT;
            const float mi = diff_i * ci * inv_kBT;
            float a = cv + DTV * (mv * lane(ldv, k));
            float bb = ci + DTV * (mi * lane(ldi, k));
            setlane(cvn, k, fminf(fmaxf(a, 0.0f), 1.0f));
            setlane(cin, k, fminf(fmaxf(bb, 0.0f), 1.0f));
        }

        const size_t o = base + (size_t)(by + ty) * W + (bx + 4 * tx);
        *(float4*)&out[o]       = cvn;
        *(float4*)&out[fld + o] = cin;
    }
}

extern "C" void kernel_launch(void* const* d_in, const int* in_sizes, int n_in,
                              void* d_out, int out_size)
{
    const float* cv  = (const float*)d_in[0];
    const float* ci  = (const float*)d_in[1];
    const float* eta = (const float*)d_in[2];
    const float* ev  = (const float*)d_in[3];
    const float* ei  = (const float*)d_in[4];
    const float* kbt = (const float*)d_in[5];
    const float* kv  = (const float*)d_in[6];
    const float* ki  = (const float*)d_in[7];
    const float* ke  = (const float*)d_in[8];
    const float* dv  = (const float*)d_in[9];
    const float* di  = (const float*)d_in[10];
    const float* L   = (const float*)d_in[11];
    float* out = (float*)d_out;

    dim3 block(16, 16, 1);
    dim3 grid(W / TSX, W / TSY, BAT);
    irr_fused_kernel<<<grid, block>>>(cv, ci, eta, ev, ei, kbt, kv, ki, ke,
                                      dv, di, L, out);
}

// round 5
// speedup vs baseline: 3.0989x; 1.1314x over previous
#include <cuda_runtime.h>
#include <cuda_bf16.h>

// IrradiationSingleTimestep — round 4: register-rolling nested stencil.
// Block = 8 warps x 32 lanes x 4 floats = full 1024-wide row; marches 8 rows.
// All field/dF rows in registers; x-neighbors via shfl; warp-edge scalars via
// a tiny smem exchange. Nested Laplacian pipelined: dF row ri computed at
// iter i, output row ri-1 finished one iteration later.

#define W     1024
#define BAT   8
#define RPB   8              // output rows per block
#define NW    8              // warps per block
#define EPSV  1e-6f
#define DTV   1e-2f

__device__ __forceinline__ float4 lap4(float4 c, float L, float R, float4 u, float4 d) {
    float4 r;
    r.x = L   + c.y + u.x + d.x - 4.0f * c.x;
    r.y = c.x + c.z + u.y + d.y - 4.0f * c.y;
    r.z = c.y + c.w + u.z + d.z - 4.0f * c.z;
    r.w = c.z + R   + u.w + d.w - 4.0f * c.w;
    return r;
}
__device__ __forceinline__ float lane_of(const float4& v, int k) {
    return k == 0 ? v.x : (k == 1 ? v.y : (k == 2 ? v.z : v.w));
}
__device__ __forceinline__ void set_lane(float4& v, int k, float x) {
    if (k == 0) v.x = x; else if (k == 1) v.y = x; else if (k == 2) v.z = x; else v.w = x;
}

__global__ __launch_bounds__(NW * 32, 2)
void irr_roll_kernel(const float* __restrict__ cv_g,
                     const float* __restrict__ ci_g,
                     const float* __restrict__ eta_g,
                     const float* __restrict__ p_ev,
                     const float* __restrict__ p_ei,
                     const float* __restrict__ p_kbt,
                     const float* __restrict__ p_kv,
                     const float* __restrict__ p_ki,
                     const float* __restrict__ p_ke,
                     const float* __restrict__ p_dv,
                     const float* __restrict__ p_di,
                     const float* __restrict__ p_L,
                     float* __restrict__ out)
{
    // Warp-edge exchange: [warp][slot]  slots: 0 cv,1 ci,2 eta,3 dfv,4 dfi
    __shared__ float sL[NW][8];   // lane0 .x of each warp
    __shared__ float sR[NW][8];   // lane31 .w of each warp

    const int lane = threadIdx.x & 31;
    const int wl   = threadIdx.x >> 5;
    const int x    = (wl << 7) + (lane << 2);       // 0..1020, step 4
    const int y0   = blockIdx.y * RPB;
    const int b    = blockIdx.z;

    const size_t plane = (size_t)W * W;
    const size_t fld   = (size_t)BAT * plane;
    const size_t basec = (size_t)b * plane + x;     // plane base + column

    const float energy_v  = fabsf(*p_ev)  + 0.001f;
    const float energy_i  = fabsf(*p_ei)  + 0.001f;
    const float kBT       = fabsf(*p_kbt) + 0.001f;
    const float kappa_v   = fabsf(*p_kv)  + 0.001f;
    const float kappa_i   = fabsf(*p_ki)  + 0.001f;
    const float kappa_eta = fabsf(*p_ke)  + 0.001f;
    const float diff_v    = fabsf(*p_dv)  + 0.001f;
    const float diff_i    = fabsf(*p_di)  + 0.001f;
    const float Lp        = fabsf(*p_L)   + 0.001f;
    const float inv_kBT   = 1.0f / kBT;

#define LDROW(p, row) (*(const float4*)((p) + basec + ((size_t)((row) & (W - 1)) << 10)))

    // Rolling field rows: m1 = row ri-1, c0 = row ri, p1 = row ri+1
    float4 cvm1 = LDROW(cv_g,  y0 - 2), cv0 = LDROW(cv_g,  y0 - 1), cvp1;
    float4 cim1 = LDROW(ci_g,  y0 - 2), ci0 = LDROW(ci_g,  y0 - 1), cip1;
    float4 etm1 = LDROW(eta_g, y0 - 2), et0 = LDROW(eta_g, y0 - 1), etp1;

    // Rolling dF rows: A = ri-2, B = ri-1 (C = ri computed in-loop)
    float4 dvA, dvB, diA, diB;
    // Held x-edges of dF row B (exchanged one iteration ago)
    float eBvL = 0.f, eBvR = 0.f, eBiL = 0.f, eBiR = 0.f;

    const int wlm1 = (wl + NW - 1) & (NW - 1);
    const int wlp1 = (wl + 1) & (NW - 1);

    for (int i = 0; i < RPB + 2; i++) {
        const int ri = y0 - 1 + i;

        // Prefetch field row ri+1
        cvp1 = LDROW(cv_g,  ri + 1);
        cip1 = LDROW(ci_g,  ri + 1);
        etp1 = LDROW(eta_g, ri + 1);

        // ---- exchange field x-edges of row ri ----
        if (lane == 0)  { sL[wl][0] = cv0.x; sL[wl][1] = ci0.x; sL[wl][2] = et0.x; }
        if (lane == 31) { sR[wl][0] = cv0.w; sR[wl][1] = ci0.w; sR[wl][2] = et0.w; }
        __syncthreads();

        float cvL = __shfl_up_sync(0xffffffffu, cv0.w, 1);
        float ciL = __shfl_up_sync(0xffffffffu, ci0.w, 1);
        float etL = __shfl_up_sync(0xffffffffu, et0.w, 1);
        float cvR = __shfl_down_sync(0xffffffffu, cv0.x, 1);
        float ciR = __shfl_down_sync(0xffffffffu, ci0.x, 1);
        float etR = __shfl_down_sync(0xffffffffu, et0.x, 1);
        if (lane == 0)  { cvL = sR[wlm1][0]; ciL = sR[wlm1][1]; etL = sR[wlm1][2]; }
        if (lane == 31) { cvR = sL[wlp1][0]; ciR = sL[wlp1][1]; etR = sL[wlp1][2]; }

        // ---- dF row ri + eta_new ----
        const float4 lcv4 = lap4(cv0, cvL, cvR, cvm1, cvp1);
        const float4 lci4 = lap4(ci0, ciL, ciR, cim1, cip1);
        const float4 let4 = lap4(et0, etL, etR, etm1, etp1);

        float4 dvC, diC, en4;
        #pragma unroll
        for (int k = 0; k < 4; k++) {
            const float cv  = lane_of(cv0, k);
            const float ci  = lane_of(ci0, k);
            const float eta = lane_of(et0, k);

            const float cs  = 1.0f - cv - ci;
            const float lcv = __logf(fmaxf(cv, EPSV));
            const float lci = __logf(fmaxf(ci, EPSV));
            const float lcs = __logf(fmaxf(cs, EPSV));

            const float em1 = eta - 1.0f;
            const float h   = em1 * em1;
            const float jj  = eta * eta;

            const float dfs_dcv = energy_v + kBT * (lcv - lcs);
            const float dfs_dci = energy_i + kBT * (lci - lcs);

            set_lane(dvC, k, h * dfs_dcv + jj * (2.0f * (cv - 1.0f)) - kappa_v * lane_of(lcv4, k));
            set_lane(diC, k, h * dfs_dci + jj * (2.0f * ci)          - kappa_i * lane_of(lci4, k));

            const float fs = energy_v * cv + energy_i * ci
                           + kBT * (cv * lcv + ci * lci + cs * lcs);
            const float cq = cv - 1.0f;
            const float fv = cq * cq + ci * ci;
            const float dFe = fs * (2.0f * em1) + fv * (2.0f * eta)
                            - kappa_eta * lane_of(let4, k);
            set_lane(en4, k, fminf(fmaxf(eta - DTV * (Lp * dFe), 0.0f), 1.0f));
        }

        // eta_new store (row ri interior <=> i in [1, RPB])
        if (i >= 1 && i <= RPB) {
            *(float4*)&out[2 * fld + basec + ((size_t)ri << 10)] = en4;
        }

        // ---- exchange dF x-edges of row ri ----
        if (lane == 0)  { sL[wl][3] = dvC.x; sL[wl][4] = diC.x; }
        if (lane == 31) { sR[wl][3] = dvC.w; sR[wl][4] = diC.w; }
        __syncthreads();

        float eCvL = __shfl_up_sync(0xffffffffu, dvC.w, 1);
        float eCiL = __shfl_up_sync(0xffffffffu, diC.w, 1);
        float eCvR = __shfl_down_sync(0xffffffffu, dvC.x, 1);
        float eCiR = __shfl_down_sync(0xffffffffu, diC.x, 1);
        if (lane == 0)  { eCvL = sR[wlm1][3]; eCiL = sR[wlm1][4]; }
        if (lane == 31) { eCvR = sL[wlp1][3]; eCiR = sL[wlp1][4]; }

        // ---- output row ro = ri-1 (needs dF rows A,B,C and fields at B) ----
        if (i >= 2) {
            const int ro = ri - 1;
            const float4 ldv = lap4(dvB, eBvL, eBvR, dvA, dvC);
            const float4 ldi = lap4(diB, eBiL, eBiR, diA, diC);

            float4 cvn, cin;
            #pragma unroll
            for (int k = 0; k < 4; k++) {
                const float cv = lane_of(cvm1, k);   // field row ri-1 = ro
                const float ci = lane_of(cim1, k);
                const float mv = diff_v * cv * inv_kBT;
                const float mi = diff_i * ci * inv_kBT;
                set_lane(cvn, k, fminf(fmaxf(cv + DTV * (mv * lane_of(ldv, k)), 0.0f), 1.0f));
                set_lane(cin, k, fminf(fmaxf(ci + DTV * (mi * lane_of(ldi, k)), 0.0f), 1.0f));
            }
            const size_t o = basec + ((size_t)ro << 10);
            *(float4*)&out[o]       = cvn;
            *(float4*)&out[fld + o] = cin;
        }

        // ---- rotate ----
        dvA = dvB; dvB = dvC; diA = diB; diB = diC;
        eBvL = eCvL; eBvR = eCvR; eBiL = eCiL; eBiR = eCiR;
        cvm1 = cv0; cv0 = cvp1;
        cim1 = ci0; ci0 = cip1;
        etm1 = et0; et0 = etp1;
    }
#undef LDROW
}

extern "C" void kernel_launch(void* const* d_in, const int* in_sizes, int n_in,
                              void* d_out, int out_size)
{
    const float* cv  = (const float*)d_in[0];
    const float* ci  = (const float*)d_in[1];
    const float* eta = (const float*)d_in[2];
    const float* ev  = (const float*)d_in[3];
    const float* ei  = (const float*)d_in[4];
    const float* kbt = (const float*)d_in[5];
    const float* kv  = (const float*)d_in[6];
    const float* ki  = (const float*)d_in[7];
    const float* ke  = (const float*)d_in[8];
    const float* dv  = (const float*)d_in[9];
    const float* di  = (const float*)d_in[10];
    const float* L   = (const float*)d_in[11];
    float* out = (float*)d_out;

    dim3 block(NW * 32, 1, 1);
    dim3 grid(1, W / RPB, BAT);
    irr_roll_kernel<<<grid, block>>>(cv, ci, eta, ev, ei, kbt, kv, ki, ke,
                                     dv, di, L, out);
}